// round 9
// baseline (speedup 1.0000x reference)
#include <cuda_runtime.h>
#include <cstdint>

#define B_ 128
#define T_ 64
#define D_ 256
#define H_ 256
#define NT 512
#define NPAIR 64
#define HH (H_ * H_)

#define BAR_PART 1
#define BAR_ACT  2
#define BAR_RED  3

// Warp-specialized, layer-pipelined persistent RNN.
// 128 CTAs (64 producer = layer 0, 64 consumer = layer 1), 512 threads each.
//   tid 256-511: 8 GEMM warps. thread (q = gt&63 -> 4 output cols,
//     kc = gt>>6 -> 64 k-rows as 16 groups of 4). Streams weights through
//     4x float4[4] register buffers, 4-group lookahead; after each stage it
//     arrives BAR_PART, prefetches the NEXT stage's first 4 groups, then
//     waits BAR_ACT. The reduce is hidden under those prefetch loads.
//   tid 0-255: 8 reduce warps. float2-grain reduction of part[4][2][64],
//     bias + activation, activation publish, h0 handoff (producer) /
//     output stores + flag acquire (consumer), bias/x prefetch in slack.

__device__ float g_h0buf[NPAIR][T_][2][H_];
__device__ int   g_flags[NPAIR * 32];

__device__ __forceinline__ void bar_arrive(int id, int cnt) {
    asm volatile("bar.arrive %0, %1;" :: "r"(id), "r"(cnt) : "memory");
}
__device__ __forceinline__ void bar_wait(int id, int cnt) {
    asm volatile("bar.sync %0, %1;" :: "r"(id), "r"(cnt) : "memory");
}
__device__ __forceinline__ void prefetchL1(const void* p) {
    asm volatile("prefetch.global.L1 [%0];" :: "l"(p));
}

__device__ __forceinline__ void f4fma(float4& a, float s, const float4 w) {
    a.x = fmaf(s, w.x, a.x); a.y = fmaf(s, w.y, a.y);
    a.z = fmaf(s, w.z, a.z); a.w = fmaf(s, w.w, a.w);
}
__device__ __forceinline__ void fma_grp(const float4 (&w)[4], const float4 A0,
                                        const float4 A1, float4& c0, float4& c1) {
    f4fma(c0, A0.x, w[0]); f4fma(c1, A1.x, w[0]);
    f4fma(c0, A0.y, w[1]); f4fma(c1, A1.y, w[1]);
    f4fma(c0, A0.z, w[2]); f4fma(c1, A1.z, w[2]);
    f4fma(c0, A0.w, w[3]); f4fma(c1, A1.w, w[3]);
}
__device__ __forceinline__ void ld_grp(float4 (&w)[4], const float4* __restrict__ Wq, int g) {
    #pragma unroll
    for (int k = 0; k < 4; ++k) w[k] = Wq[g * 256 + k * 64];
}

// Stage over ONE 256-k matrix (16 groups). b0..b3 hold groups 0-3 on entry.
__device__ __forceinline__ void stage16_(
    const float4* __restrict__ W,
    const float4* __restrict__ a0, const float4* __restrict__ a1,
    float4 (&b0)[4], float4 (&b1)[4], float4 (&b2)[4], float4 (&b3)[4],
    float4& acc0, float4& acc1)
{
    #pragma unroll
    for (int g = 0; g < 12; g += 4) {
        fma_grp(b0, a0[g+0], a1[g+0], acc0, acc1); ld_grp(b0, W, g+4);
        fma_grp(b1, a0[g+1], a1[g+1], acc0, acc1); ld_grp(b1, W, g+5);
        fma_grp(b2, a0[g+2], a1[g+2], acc0, acc1); ld_grp(b2, W, g+6);
        fma_grp(b3, a0[g+3], a1[g+3], acc0, acc1); ld_grp(b3, W, g+7);
    }
    fma_grp(b0, a0[12], a1[12], acc0, acc1);
    fma_grp(b1, a0[13], a1[13], acc0, acc1);
    fma_grp(b2, a0[14], a1[14], acc0, acc1);
    fma_grp(b3, a0[15], a1[15], acc0, acc1);
}

// Stage A: W1 (h-act, smem, ready) then W2 (in-act, maybe gmem). b holds W1 g0-3.
__device__ __forceinline__ void stageA_(
    const float4* __restrict__ W1,
    const float4* __restrict__ h0, const float4* __restrict__ h1,
    const float4* __restrict__ W2,
    const float4* __restrict__ i0, const float4* __restrict__ i1,
    float4 (&b0)[4], float4 (&b1)[4], float4 (&b2)[4], float4 (&b3)[4],
    float4& acc0, float4& acc1)
{
    #pragma unroll
    for (int g = 0; g < 12; g += 4) {
        fma_grp(b0, h0[g+0], h1[g+0], acc0, acc1); ld_grp(b0, W1, g+4);
        fma_grp(b1, h0[g+1], h1[g+1], acc0, acc1); ld_grp(b1, W1, g+5);
        fma_grp(b2, h0[g+2], h1[g+2], acc0, acc1); ld_grp(b2, W1, g+6);
        fma_grp(b3, h0[g+3], h1[g+3], acc0, acc1); ld_grp(b3, W1, g+7);
    }
    fma_grp(b0, h0[12], h1[12], acc0, acc1); ld_grp(b0, W2, 0);
    fma_grp(b1, h0[13], h1[13], acc0, acc1); ld_grp(b1, W2, 1);
    fma_grp(b2, h0[14], h1[14], acc0, acc1); ld_grp(b2, W2, 2);
    fma_grp(b3, h0[15], h1[15], acc0, acc1); ld_grp(b3, W2, 3);
    #pragma unroll
    for (int g = 0; g < 12; g += 4) {
        fma_grp(b0, i0[g+0], i1[g+0], acc0, acc1); ld_grp(b0, W2, g+4);
        fma_grp(b1, i0[g+1], i1[g+1], acc0, acc1); ld_grp(b1, W2, g+5);
        fma_grp(b2, i0[g+2], i1[g+2], acc0, acc1); ld_grp(b2, W2, g+6);
        fma_grp(b3, i0[g+3], i1[g+3], acc0, acc1); ld_grp(b3, W2, g+7);
    }
    fma_grp(b0, i0[12], i1[12], acc0, acc1);
    fma_grp(b1, i0[13], i1[13], acc0, acc1);
    fma_grp(b2, i0[14], i1[14], acc0, acc1);
    fma_grp(b3, i0[15], i1[15], acc0, acc1);
}

__global__ void reset_flags_kernel() {
    g_flags[threadIdx.x * 32] = 0;
}

__global__ void __launch_bounds__(NT, 1)
rnn_ws_kernel(const float* __restrict__ x,       // [B,T,D]
              const float* __restrict__ hidden,  // [L,B,H]
              const float* __restrict__ Win0,    // [T,D,H]
              const float* __restrict__ Wh0,     // [T,3,H,H]
              const float* __restrict__ b0in,    // [T,3,H]
              const float* __restrict__ Win1,    // [T,H,H]
              const float* __restrict__ Wh1,     // [T,3,H,H]
              const float* __restrict__ b1in,    // [T,3,H]
              float* __restrict__ out,           // [B,T,H]
              float* __restrict__ hout)          // [L,B,H]
{
    __shared__ __align__(16) float xs[2][H_];
    __shared__ __align__(16) float hs[2][H_];
    __shared__ __align__(16) float n0s[2][H_];
    __shared__ __align__(16) float n1s[2][H_];
    __shared__ __align__(16) float bs[2][3][H_];
    __shared__ __align__(16) float4 part[4][2][64];

    const int tid = threadIdx.x;
    const int pair = blockIdx.x >> 1;
    const int layer = blockIdx.x & 1;
    const int r0 = pair * 2;

    const float* Wi_base   = layer ? Win1 : Win0;
    const float* Wh_base   = layer ? Wh1 : Wh0;
    const float* bias_base = layer ? b1in : b0in;

    // ---- init (all threads) ----
    {
        int row = tid >> 8, j = tid & 255;
        hs[row][j] = hidden[((size_t)layer * B_ + r0 + row) * H_ + j];
        if (layer == 0)
            xs[row][j] = x[((size_t)(r0 + row) * T_) * D_ + j];
    }
    if (tid < 192)
        *reinterpret_cast<float4*>(&bs[0][0][0] + tid * 4) =
            *reinterpret_cast<const float4*>(bias_base + tid * 4);
    if (layer == 1 && tid == 0) {
        int v;
        do {
            asm volatile("ld.acquire.gpu.global.s32 %0, [%1];"
                         : "=r"(v) : "l"(&g_flags[pair * 32]) : "memory");
            if (v < 1) __nanosleep(64);
        } while (v < 1);
    }
    __syncthreads();

    if (tid >= 256) {
        // ================= GEMM warps =================
        const int gt = tid - 256;
        const int q = gt & 63;
        const int kc = gt >> 6;          // 0..3
        const int kc16 = kc * 16;

        const float4* hs0 = reinterpret_cast<const float4*>(hs[0]) + kc16;
        const float4* hs1 = reinterpret_cast<const float4*>(hs[1]) + kc16;
        const float4* xs0 = reinterpret_cast<const float4*>(xs[0]) + kc16;
        const float4* xs1 = reinterpret_cast<const float4*>(xs[1]) + kc16;
        const float4* n00 = reinterpret_cast<const float4*>(n0s[0]) + kc16;
        const float4* n01 = reinterpret_cast<const float4*>(n0s[1]) + kc16;
        const float4* n10 = reinterpret_cast<const float4*>(n1s[0]) + kc16;
        const float4* n11 = reinterpret_cast<const float4*>(n1s[1]) + kc16;
        const int woff = kc16 * 256 + q;

        float4 b0[4], b1[4], b2[4], b3[4];
        // bootstrap: Wh0(t=0) groups 0-3 (stage A runs Wh-segment first)
        {
            const float4* W = reinterpret_cast<const float4*>(Wh_base) + woff;
            ld_grp(b0, W, 0); ld_grp(b1, W, 1); ld_grp(b2, W, 2); ld_grp(b3, W, 3);
        }

        for (int t = 0; t < T_; ++t) {
            const float4* WqWi = reinterpret_cast<const float4*>(
                Wi_base + (size_t)t * (D_ * H_)) + woff;
            const float* WhT = Wh_base + (size_t)t * 3 * HH;
            const float4* WqWh0 = reinterpret_cast<const float4*>(WhT) + woff;
            const float4* WqWh1 = reinterpret_cast<const float4*>(WhT + HH) + woff;
            const float4* WqWh2 = reinterpret_cast<const float4*>(WhT + 2 * HH) + woff;
            const int tn = (t + 1 < T_) ? t + 1 : 0;
            const float4* WqWhN = reinterpret_cast<const float4*>(
                Wh_base + (size_t)tn * 3 * HH) + woff;

            const float4* i0;
            const float4* i1;
            if (layer == 0) { i0 = xs0; i1 = xs1; }
            else {
                i0 = reinterpret_cast<const float4*>(&g_h0buf[pair][t][0][0]) + kc16;
                i1 = reinterpret_cast<const float4*>(&g_h0buf[pair][t][1][0]) + kc16;
                // touch all lines of h0buf(t) so the Wi-segment L1-hits
                prefetchL1(i0); prefetchL1(i0 + 8);
                prefetchL1(i1); prefetchL1(i1 + 8);
            }

            // ---- stage A: h@Wh[0] + in@Wi ----
            float4 acc0 = {0.f,0.f,0.f,0.f}, acc1 = {0.f,0.f,0.f,0.f};
            stageA_(WqWh0, hs0, hs1, WqWi, i0, i1, b0, b1, b2, b3, acc0, acc1);
            part[kc][0][q] = acc0; part[kc][1][q] = acc1;
            bar_arrive(BAR_PART, NT);
            ld_grp(b0, WqWh1, 0); ld_grp(b1, WqWh1, 1);
            ld_grp(b2, WqWh1, 2); ld_grp(b3, WqWh1, 3);
            bar_wait(BAR_ACT, NT);

            // ---- stage B: n0@Wh[1] ----
            acc0 = make_float4(0.f,0.f,0.f,0.f); acc1 = acc0;
            stage16_(WqWh1, n00, n01, b0, b1, b2, b3, acc0, acc1);
            part[kc][0][q] = acc0; part[kc][1][q] = acc1;
            bar_arrive(BAR_PART, NT);
            ld_grp(b0, WqWh2, 0); ld_grp(b1, WqWh2, 1);
            ld_grp(b2, WqWh2, 2); ld_grp(b3, WqWh2, 3);
            bar_wait(BAR_ACT, NT);

            // ---- stage C: n1@Wh[2] ----
            acc0 = make_float4(0.f,0.f,0.f,0.f); acc1 = acc0;
            stage16_(WqWh2, n10, n11, b0, b1, b2, b3, acc0, acc1);
            part[kc][0][q] = acc0; part[kc][1][q] = acc1;
            bar_arrive(BAR_PART, NT);
            ld_grp(b0, WqWhN, 0); ld_grp(b1, WqWhN, 1);
            ld_grp(b2, WqWhN, 2); ld_grp(b3, WqWhN, 3);
            bar_wait(BAR_ACT, NT);
        }
    } else {
        // ================= reduce warps =================
        const int row = tid >> 7;        // 0/1
        const int q2 = tid & 127;        // float2 column index
        const float2* p2 = reinterpret_cast<const float2*>(&part[0][0][0]);
        const int pbase = ((row) * 64 + (q2 >> 1)) * 2 + (q2 & 1);
        const int pstride = 2 * 64 * 2;  // one kc slab in float2 units

        for (int t = 0; t < T_; ++t) {
            const float2* bsc = reinterpret_cast<const float2*>(&bs[t & 1][0][0]);
            const int tn = (t + 1 < T_) ? t + 1 : 0;

            // ---- node 0 reduce: tanh ----
            bar_wait(BAR_PART, NT);
            float2 s;
            {
                float2 e0 = p2[pbase], e1 = p2[pbase + pstride];
                float2 e2 = p2[pbase + 2 * pstride], e3 = p2[pbase + 3 * pstride];
                s.x = (e0.x + e1.x) + (e2.x + e3.x);
                s.y = (e0.y + e1.y) + (e2.y + e3.y);
            }
            float2 bv = bsc[q2];
            float2 v0 = make_float2(tanhf(s.x + bv.x), tanhf(s.y + bv.y));
            *reinterpret_cast<float2*>(&n0s[row][2 * q2]) = v0;
            bar_arrive(BAR_ACT, NT);

            // slack: prefetch bias(t+1)
            if (tid < 192)
                *reinterpret_cast<float4*>(&bs[(t + 1) & 1][0][0] + tid * 4) =
                    *reinterpret_cast<const float4*>(
                        bias_base + (size_t)tn * 3 * H_ + tid * 4);

            // ---- node 1 reduce: relu + n0 ----
            bar_wait(BAR_PART, NT);
            {
                float2 e0 = p2[pbase], e1 = p2[pbase + pstride];
                float2 e2 = p2[pbase + 2 * pstride], e3 = p2[pbase + 3 * pstride];
                s.x = (e0.x + e1.x) + (e2.x + e3.x);
                s.y = (e0.y + e1.y) + (e2.y + e3.y);
            }
            bv = bsc[128 + q2];
            float2 u = make_float2(fmaxf(s.x + bv.x, 0.f) + v0.x,
                                   fmaxf(s.y + bv.y, 0.f) + v0.y);
            *reinterpret_cast<float2*>(&n1s[row][2 * q2]) = u;
            bar_arrive(BAR_ACT, NT);

            // slack: producer prefetches x(t+1)
            if (layer == 0 && t + 1 < T_ && tid < 128) {
                int rr = tid >> 6, col = (tid & 63) * 4;
                *reinterpret_cast<float4*>(&xs[rr][col]) =
                    *reinterpret_cast<const float4*>(
                        &x[((size_t)(r0 + rr) * T_ + t + 1) * D_ + col]);
            }

            // ---- node 2 reduce: sigmoid + n0 ; h = 0.5*(n1+n2) ----
            bar_wait(BAR_PART, NT);
            {
                float2 e0 = p2[pbase], e1 = p2[pbase + pstride];
                float2 e2 = p2[pbase + 2 * pstride], e3 = p2[pbase + 3 * pstride];
                s.x = (e0.x + e1.x) + (e2.x + e3.x);
                s.y = (e0.y + e1.y) + (e2.y + e3.y);
            }
            bv = bsc[256 + q2];
            float2 g = make_float2(1.f / (1.f + expf(-(s.x + bv.x))) + v0.x,
                                   1.f / (1.f + expf(-(s.y + bv.y))) + v0.y);
            float2 hn = make_float2(0.5f * (u.x + g.x), 0.5f * (u.y + g.y));
            *reinterpret_cast<float2*>(&hs[row][2 * q2]) = hn;
            if (layer == 0) {
                float2* dst = reinterpret_cast<float2*>(&g_h0buf[pair][t][row][2 * q2]);
                __stcg(&dst->x, hn.x);  __stcg(&dst->y, hn.y);
                __threadfence();
                bar_wait(BAR_RED, 256);
                if (tid == 0)
                    asm volatile("st.release.gpu.global.s32 [%0], %1;"
                                 :: "l"(&g_flags[pair * 32]), "r"(t + 1) : "memory");
            } else {
                *reinterpret_cast<float2*>(
                    out + ((size_t)(r0 + row) * T_ + t) * H_ + 2 * q2) = hn;
                if (tid == 0 && t + 1 < T_) {
                    int v;
                    do {
                        asm volatile("ld.acquire.gpu.global.s32 %0, [%1];"
                                     : "=r"(v) : "l"(&g_flags[pair * 32]) : "memory");
                        if (v < t + 2) __nanosleep(64);
                    } while (v < t + 2);
                }
            }
            bar_arrive(BAR_ACT, NT);
        }
    }

    __syncthreads();
    {
        int row = tid >> 8, j = tid & 255;
        hout[((size_t)layer * B_ + r0 + row) * H_ + j] = hs[row][j];
    }
}

extern "C" void kernel_launch(void* const* d_in, const int* in_sizes, int n_in,
                              void* d_out, int out_size) {
    const float* x      = (const float*)d_in[0];
    const float* hidden = (const float*)d_in[1];
    const float* Win0   = (const float*)d_in[2];
    const float* Wh0    = (const float*)d_in[3];
    const float* b0     = (const float*)d_in[4];
    const float* Win1   = (const float*)d_in[5];
    const float* Wh1    = (const float*)d_in[6];
    const float* b1     = (const float*)d_in[7];

    float* out  = (float*)d_out;                  // [B,T,H]
    float* hout = out + (size_t)B_ * T_ * H_;     // [L,B,H]

    reset_flags_kernel<<<1, NPAIR>>>();
    rnn_ws_kernel<<<2 * NPAIR, NT>>>(x, hidden, Win0, Wh0, b0,
                                     Win1, Wh1, b1, out, hout);
}